// round 10
// baseline (speedup 1.0000x reference)
#include <cuda_runtime.h>
#include <cstdint>

#define NSPOT 50000
#define NGENE 2000
#define HID   64
#define NEDGE 800000
#define BN_EPS 1e-5f

// ---------------- device scratch (no allocation allowed) ----------------
__device__ float g_z[NSPOT * HID];        // raw z, later reused for u_nb (tf32-rounded)
__device__ float g_uself[NSPOT * HID];    // relu(h@Ws1+bs1), tf32-rounded
__device__ float g_agg[NSPOT * HID];      // neighbor raw sums
__device__ int   g_cnt[NSPOT];
__device__ float g_part[500 * 128];
__device__ float g_sc[HID];               // gamma * rstd
__device__ float g_sh[HID];               // beta - mean * gamma * rstd
__device__ unsigned g_bnctr;              // last-block counter (wraps to 0)
__device__ float g_wb[2 * HID * NGENE];   // tf32-rounded Ws2 | We2

// ---------------- tf32 helpers ------------------------------------------
__device__ __forceinline__ uint32_t f2tf(float f) {
    uint32_t r; asm("cvt.rna.tf32.f32 %0, %1;" : "=r"(r) : "f"(f)); return r;
}
__device__ __forceinline__ float roundtf(float f) {
    return __uint_as_float(f2tf(f));
}
__device__ __forceinline__ void mma8(float* c, const uint32_t* a, const uint32_t* b) {
    asm volatile(
        "mma.sync.aligned.m16n8k8.row.col.f32.tf32.tf32.f32 "
        "{%0,%1,%2,%3}, {%4,%5,%6,%7}, {%8,%9}, {%0,%1,%2,%3};"
        : "+f"(c[0]), "+f"(c[1]), "+f"(c[2]), "+f"(c[3])
        : "r"(a[0]), "r"(a[1]), "r"(a[2]), "r"(a[3]), "r"(b[0]), "r"(b[1]));
}
__device__ __forceinline__ void cpa16(uint32_t s, const void* g, bool pred) {
    int sz = pred ? 16 : 0;
    asm volatile("cp.async.cg.shared.global [%0], [%1], 16, %2;"
                 :: "r"(s), "l"(g), "r"(sz));
}

// ============ generic cp.async double-buffered TF32 GEMM ================
// BK=32. C = A@B + bias. zfill handles ragged M/N/K.
// CVT: convert f32->tf32 when reading smem (needed if operands not pre-rounded).
template<int BM, int BN, bool RELU, bool CVT, int MINB>
__global__ __launch_bounds__(256, MINB)
void gemm_db(const float* __restrict__ A, const float* __restrict__ B,
             const float* __restrict__ bias, float* __restrict__ C,
             int M, int N, int K)
{
    constexpr int BK = 32;
    constexpr int ASTR = BK + 4;             // 36
    constexpr int BSTR = BN + 8;
    constexpr int BCH  = BN / 4;             // float4 chunks per B row
    constexpr int STAGE = BM * ASTR + BK * BSTR;
    constexpr int WARPS_N = BN / 32;
    constexpr int WARPS_M = 8 / WARPS_N;
    constexpr int WM = BM / WARPS_M;
    constexpr int MT = WM / 16;

    extern __shared__ __align__(16) float dsm[];

    const int tid = threadIdx.x;
    const int lane = tid & 31, wid = tid >> 5;
    const int g = lane >> 2, tg = lane & 3;
    const int rowBase = blockIdx.y * BM;
    const int colBase = blockIdx.x * BN;
    const int mW = (wid / WARPS_N) * WM;
    const int nW = (wid % WARPS_N) * 32;

    float acc[MT][4][4];
#pragma unroll
    for (int i = 0; i < MT; i++)
#pragma unroll
        for (int j = 0; j < 4; j++)
#pragma unroll
            for (int q = 0; q < 4; q++) acc[i][j][q] = 0.f;

    const int KT = (K + BK - 1) / BK;

    auto rd = [](float v) -> uint32_t {
        return CVT ? f2tf(v) : __float_as_uint(v);
    };

    auto loadTiles = [&](int buf, int k0) {
        float* Ab = dsm + buf * STAGE;
        float* Bb = Ab + BM * ASTR;
#pragma unroll
        for (int ii = 0; ii < (BM * 8) / 256; ii++) {     // A float4 chunks
            int i = tid + ii * 256;
            int m = i >> 3, k4 = (i & 7) * 4;
            int r = rowBase + m, gk = k0 + k4;
            cpa16((uint32_t)__cvta_generic_to_shared(Ab + m * ASTR + k4),
                  A + (size_t)r * K + gk, (r < M) && (gk < K));
        }
#pragma unroll
        for (int ii = 0; ii < (BK * BCH) / 256; ii++) {   // B chunks
            int i = tid + ii * 256;
            int kk = i / BCH, n4 = (i % BCH) * 4;
            int gk = k0 + kk, c = colBase + n4;
            cpa16((uint32_t)__cvta_generic_to_shared(Bb + kk * BSTR + n4),
                  B + (size_t)gk * N + c, (gk < K) && (c < N));
        }
    };

    loadTiles(0, 0);
    asm volatile("cp.async.commit_group;");
    int buf = 0;
    for (int kt = 0; kt < KT; kt++) {
        if (kt + 1 < KT) loadTiles(buf ^ 1, (kt + 1) * BK);
        asm volatile("cp.async.commit_group;");
        asm volatile("cp.async.wait_group 1;");
        __syncthreads();
        const float* Ab = dsm + buf * STAGE;
        const float* Bb = Ab + BM * ASTR;
#pragma unroll
        for (int ks = 0; ks < BK / 8; ks++) {
            uint32_t a[MT][4], b[4][2];
#pragma unroll
            for (int i = 0; i < MT; i++) {
                int r0 = mW + i * 16 + g;
                a[i][0] = rd(Ab[r0 * ASTR + ks * 8 + tg]);
                a[i][1] = rd(Ab[(r0 + 8) * ASTR + ks * 8 + tg]);
                a[i][2] = rd(Ab[r0 * ASTR + ks * 8 + tg + 4]);
                a[i][3] = rd(Ab[(r0 + 8) * ASTR + ks * 8 + tg + 4]);
            }
#pragma unroll
            for (int j = 0; j < 4; j++) {
                b[j][0] = rd(Bb[(ks * 8 + tg) * BSTR + nW + j * 8 + g]);
                b[j][1] = rd(Bb[(ks * 8 + tg + 4) * BSTR + nW + j * 8 + g]);
            }
#pragma unroll
            for (int i = 0; i < MT; i++)
#pragma unroll
                for (int j = 0; j < 4; j++)
                    mma8(acc[i][j], a[i], b[j]);
        }
        __syncthreads();
        buf ^= 1;
    }

#pragma unroll
    for (int i = 0; i < MT; i++) {
        int r0 = rowBase + mW + i * 16 + g;
        int r1 = r0 + 8;
#pragma unroll
        for (int j = 0; j < 4; j++) {
            int c = colBase + nW + j * 8 + tg * 2;
            if (c >= N) continue;
            float bi0 = __ldg(bias + c), bi1 = __ldg(bias + c + 1);
            if (r0 < M) {
                float o0 = acc[i][j][0] + bi0, o1 = acc[i][j][1] + bi1;
                if (RELU) { o0 = fmaxf(o0, 0.f); o1 = fmaxf(o1, 0.f); }
                *reinterpret_cast<float2*>(C + (size_t)r0 * N + c) = make_float2(o0, o1);
            }
            if (r1 < M) {
                float o2 = acc[i][j][2] + bi0, o3 = acc[i][j][3] + bi1;
                if (RELU) { o2 = fmaxf(o2, 0.f); o3 = fmaxf(o3, 0.f); }
                *reinterpret_cast<float2*>(C + (size_t)r1 * N + c) = make_float2(o2, o3);
            }
        }
    }
}

// ======== generic TF32 GEMM (single-buffered, static smem) ===============
// AMODE: 0 = none, 2 = per-row 1/cnt on A.  ROUND: tf32-round stored outputs.
template<int BM, int BN, int BK, bool RELU, int AMODE, bool ROUND>
__global__ __launch_bounds__(256)
void gemm_tf32(const float* __restrict__ A, const float* __restrict__ B,
               const float* __restrict__ bias, float* __restrict__ C,
               int M, int N, int K)
{
    constexpr int WARPS_N = BN / 32;
    constexpr int WARPS_M = 8 / WARPS_N;
    constexpr int WM = BM / WARPS_M;
    constexpr int MT = WM / 16;
    constexpr int NT = 4;
    constexpr int ASTR = BK + 4;
    constexpr int BSTR = BN + 8;

    __shared__ __align__(16) uint32_t As[BM * ASTR];
    __shared__ __align__(16) uint32_t Bs[BK * BSTR];

    const int tid = threadIdx.x;
    const int lane = tid & 31, wid = tid >> 5;
    const int g = lane >> 2, tg = lane & 3;
    const int rowBase = blockIdx.y * BM;
    const int colBase = blockIdx.x * BN;
    const int mW = (wid / WARPS_N) * WM;
    const int nW = (wid % WARPS_N) * 32;

    float acc[MT][NT][4];
#pragma unroll
    for (int i = 0; i < MT; i++)
#pragma unroll
        for (int j = 0; j < NT; j++)
#pragma unroll
            for (int q = 0; q < 4; q++) acc[i][j][q] = 0.f;

    for (int k0 = 0; k0 < K; k0 += BK) {
#pragma unroll 2
        for (int i = tid; i < BM * (BK / 4); i += 256) {
            int m = i / (BK / 4), k4 = (i % (BK / 4)) * 4;
            int r = rowBase + m;
            uint4 v = {0u, 0u, 0u, 0u};
            if (r < M) {
                float4 f = *reinterpret_cast<const float4*>(A + (size_t)r * K + k0 + k4);
                if (AMODE == 2) {
                    float inv = 1.0f / fmaxf((float)__ldg(&g_cnt[r]), 1.0f);
                    f.x *= inv; f.y *= inv; f.z *= inv; f.w *= inv;
                }
                v.x = f2tf(f.x); v.y = f2tf(f.y); v.z = f2tf(f.z); v.w = f2tf(f.w);
            }
            *reinterpret_cast<uint4*>(&As[m * ASTR + k4]) = v;
        }
#pragma unroll 2
        for (int i = tid; i < BK * (BN / 4); i += 256) {
            int kk = i / (BN / 4), n4 = (i % (BN / 4)) * 4;
            int c = colBase + n4;
            uint4 v = {0u, 0u, 0u, 0u};
            if (c < N) {
                float4 f = *reinterpret_cast<const float4*>(B + (size_t)(k0 + kk) * N + c);
                v.x = f2tf(f.x); v.y = f2tf(f.y); v.z = f2tf(f.z); v.w = f2tf(f.w);
            }
            *reinterpret_cast<uint4*>(&Bs[kk * BSTR + n4]) = v;
        }
        __syncthreads();
#pragma unroll
        for (int ks = 0; ks < BK / 8; ks++) {
            uint32_t a[MT][4], b[NT][2];
#pragma unroll
            for (int i = 0; i < MT; i++) {
                int r0 = mW + i * 16 + g;
                a[i][0] = As[r0 * ASTR + ks * 8 + tg];
                a[i][1] = As[(r0 + 8) * ASTR + ks * 8 + tg];
                a[i][2] = As[r0 * ASTR + ks * 8 + tg + 4];
                a[i][3] = As[(r0 + 8) * ASTR + ks * 8 + tg + 4];
            }
#pragma unroll
            for (int j = 0; j < NT; j++) {
                b[j][0] = Bs[(ks * 8 + tg) * BSTR + nW + j * 8 + g];
                b[j][1] = Bs[(ks * 8 + tg + 4) * BSTR + nW + j * 8 + g];
            }
#pragma unroll
            for (int i = 0; i < MT; i++)
#pragma unroll
                for (int j = 0; j < NT; j++)
                    mma8(acc[i][j], a[i], b[j]);
        }
        __syncthreads();
    }

#pragma unroll
    for (int i = 0; i < MT; i++) {
        int r0 = rowBase + mW + i * 16 + g;
        int r1 = r0 + 8;
#pragma unroll
        for (int j = 0; j < NT; j++) {
            int c = colBase + nW + j * 8 + tg * 2;
            if (c >= N) continue;
            float bi0 = __ldg(bias + c), bi1 = __ldg(bias + c + 1);
            float o0 = acc[i][j][0] + bi0, o1 = acc[i][j][1] + bi1;
            float o2 = acc[i][j][2] + bi0, o3 = acc[i][j][3] + bi1;
            if (RELU) {
                o0 = fmaxf(o0, 0.f); o1 = fmaxf(o1, 0.f);
                o2 = fmaxf(o2, 0.f); o3 = fmaxf(o3, 0.f);
            }
            if (ROUND) {
                o0 = roundtf(o0); o1 = roundtf(o1);
                o2 = roundtf(o2); o3 = roundtf(o3);
            }
            if (r0 < M)
                *reinterpret_cast<float2*>(C + (size_t)r0 * N + c) = make_float2(o0, o1);
            if (r1 < M)
                *reinterpret_cast<float2*>(C + (size_t)r1 * N + c) = make_float2(o2, o3);
        }
    }
}

// ======== fused encoder tail: BNReLU(z)@W2 -> h ; heads ; pos ============
__global__ __launch_bounds__(256)
void fused_enc(const float* __restrict__ z,
               const float* __restrict__ W2,  const float* __restrict__ b2,
               const float* __restrict__ Wp1, const float* __restrict__ bp1,
               const float* __restrict__ Ws1, const float* __restrict__ bs1,
               const float* __restrict__ Wp2, const float* __restrict__ bp2,
               float* __restrict__ h_out, float* __restrict__ pos_out,
               float* __restrict__ uself, int M)
{
    extern __shared__ __align__(16) uint32_t fsm[];
    uint32_t* Zs  = fsm;                  // 128 x 68 (A layout, tf32)
    uint32_t* W2s = Zs + 128 * 68;        // 64 x 72  (B layout)
    uint32_t* W13 = W2s + 64 * 72;        // 64 x 136 (B layout: Wp1|Ws1)
    float* upos = reinterpret_cast<float*>(W13);   // reuse: 128 x 65

    const int tid = threadIdx.x;
    const int lane = tid & 31, wid = tid >> 5;
    const int g = lane >> 2, tg = lane & 3;
    const int rowBase = blockIdx.x * 128;

#pragma unroll
    for (int ii = 0; ii < 8; ii++) {
        int i = tid + ii * 256;
        int m = i >> 4, k4 = (i & 15) * 4;
        int r = rowBase + m;
        uint4 v = {0u, 0u, 0u, 0u};
        if (r < M) {
            float4 f = *reinterpret_cast<const float4*>(z + (size_t)r * HID + k4);
            f.x = fmaxf(fmaf(f.x, g_sc[k4+0], g_sh[k4+0]), 0.f);
            f.y = fmaxf(fmaf(f.y, g_sc[k4+1], g_sh[k4+1]), 0.f);
            f.z = fmaxf(fmaf(f.z, g_sc[k4+2], g_sh[k4+2]), 0.f);
            f.w = fmaxf(fmaf(f.w, g_sc[k4+3], g_sh[k4+3]), 0.f);
            v.x = f2tf(f.x); v.y = f2tf(f.y); v.z = f2tf(f.z); v.w = f2tf(f.w);
        }
        *reinterpret_cast<uint4*>(&Zs[m * 68 + k4]) = v;
    }
#pragma unroll
    for (int ii = 0; ii < 4; ii++) {
        int i = tid + ii * 256;
        int kk = i >> 4, n4 = (i & 15) * 4;
        float4 f = *reinterpret_cast<const float4*>(W2 + kk * HID + n4);
        uint4 v; v.x = f2tf(f.x); v.y = f2tf(f.y); v.z = f2tf(f.z); v.w = f2tf(f.w);
        *reinterpret_cast<uint4*>(&W2s[kk * 72 + n4]) = v;
    }
#pragma unroll
    for (int ii = 0; ii < 8; ii++) {
        int i = tid + ii * 256;
        int kk = i >> 5, n4 = (i & 31) * 4;
        const float* src = (n4 < 64) ? (Wp1 + kk * HID + n4) : (Ws1 + kk * HID + n4 - 64);
        float4 f = *reinterpret_cast<const float4*>(src);
        uint4 v; v.x = f2tf(f.x); v.y = f2tf(f.y); v.z = f2tf(f.z); v.w = f2tf(f.w);
        *reinterpret_cast<uint4*>(&W13[kk * 136 + n4]) = v;
    }
    __syncthreads();

    // --- stage 1: h = Zs @ W2 + b2 ---
    {
        const int mW = (wid >> 1) * 32;
        const int nW = (wid & 1) * 32;
        float acc[2][4][4];
#pragma unroll
        for (int i = 0; i < 2; i++)
#pragma unroll
            for (int j = 0; j < 4; j++)
#pragma unroll
                for (int q = 0; q < 4; q++) acc[i][j][q] = 0.f;
#pragma unroll
        for (int ks = 0; ks < 8; ks++) {
            uint32_t a[2][4], b[4][2];
#pragma unroll
            for (int i = 0; i < 2; i++) {
                int r0 = mW + i * 16 + g;
                a[i][0] = Zs[r0 * 68 + ks * 8 + tg];
                a[i][1] = Zs[(r0 + 8) * 68 + ks * 8 + tg];
                a[i][2] = Zs[r0 * 68 + ks * 8 + tg + 4];
                a[i][3] = Zs[(r0 + 8) * 68 + ks * 8 + tg + 4];
            }
#pragma unroll
            for (int j = 0; j < 4; j++) {
                b[j][0] = W2s[(ks * 8 + tg) * 72 + nW + j * 8 + g];
                b[j][1] = W2s[(ks * 8 + tg + 4) * 72 + nW + j * 8 + g];
            }
#pragma unroll
            for (int i = 0; i < 2; i++)
#pragma unroll
                for (int j = 0; j < 4; j++)
                    mma8(acc[i][j], a[i], b[j]);
        }
        __syncthreads();
#pragma unroll
        for (int i = 0; i < 2; i++) {
            int lr0 = mW + i * 16 + g, lr1 = lr0 + 8;
            int r0 = rowBase + lr0, r1 = rowBase + lr1;
#pragma unroll
            for (int j = 0; j < 4; j++) {
                int c = nW + j * 8 + tg * 2;
                float bi0 = __ldg(b2 + c), bi1 = __ldg(b2 + c + 1);
                float h0 = acc[i][j][0] + bi0, h1 = acc[i][j][1] + bi1;
                float h2 = acc[i][j][2] + bi0, h3 = acc[i][j][3] + bi1;
                Zs[lr0 * 68 + c] = f2tf(h0); Zs[lr0 * 68 + c + 1] = f2tf(h1);
                Zs[lr1 * 68 + c] = f2tf(h2); Zs[lr1 * 68 + c + 1] = f2tf(h3);
                if (r0 < M)
                    *reinterpret_cast<float2*>(h_out + (size_t)r0 * HID + c) = make_float2(h0, h1);
                if (r1 < M)
                    *reinterpret_cast<float2*>(h_out + (size_t)r1 * HID + c) = make_float2(h2, h3);
            }
        }
    }
    __syncthreads();

    // --- stage 2: [u_pos | u_self] = h @ [Wp1|Ws1] ---
    {
        const int mW = (wid >> 2) * 64;
        const int nW = (wid & 3) * 32;
        float acc[4][4][4];
#pragma unroll
        for (int i = 0; i < 4; i++)
#pragma unroll
            for (int j = 0; j < 4; j++)
#pragma unroll
                for (int q = 0; q < 4; q++) acc[i][j][q] = 0.f;
#pragma unroll
        for (int ks = 0; ks < 8; ks++) {
            uint32_t a[4][4], b[4][2];
#pragma unroll
            for (int i = 0; i < 4; i++) {
                int r0 = mW + i * 16 + g;
                a[i][0] = Zs[r0 * 68 + ks * 8 + tg];
                a[i][1] = Zs[(r0 + 8) * 68 + ks * 8 + tg];
                a[i][2] = Zs[r0 * 68 + ks * 8 + tg + 4];
                a[i][3] = Zs[(r0 + 8) * 68 + ks * 8 + tg + 4];
            }
#pragma unroll
            for (int j = 0; j < 4; j++) {
                b[j][0] = W13[(ks * 8 + tg) * 136 + nW + j * 8 + g];
                b[j][1] = W13[(ks * 8 + tg + 4) * 136 + nW + j * 8 + g];
            }
#pragma unroll
            for (int i = 0; i < 4; i++)
#pragma unroll
                for (int j = 0; j < 4; j++)
                    mma8(acc[i][j], a[i], b[j]);
        }
        __syncthreads();
#pragma unroll
        for (int i = 0; i < 4; i++) {
            int lr0 = mW + i * 16 + g, lr1 = lr0 + 8;
            int r0 = rowBase + lr0, r1 = rowBase + lr1;
#pragma unroll
            for (int j = 0; j < 4; j++) {
                int c = nW + j * 8 + tg * 2;
                if (c < 64) {
                    float bi0 = __ldg(bp1 + c), bi1 = __ldg(bp1 + c + 1);
                    upos[lr0 * 65 + c]     = fmaxf(acc[i][j][0] + bi0, 0.f);
                    upos[lr0 * 65 + c + 1] = fmaxf(acc[i][j][1] + bi1, 0.f);
                    upos[lr1 * 65 + c]     = fmaxf(acc[i][j][2] + bi0, 0.f);
                    upos[lr1 * 65 + c + 1] = fmaxf(acc[i][j][3] + bi1, 0.f);
                } else {
                    int cc = c - 64;
                    float bi0 = __ldg(bs1 + cc), bi1 = __ldg(bs1 + cc + 1);
                    // tf32-rounded at write: xs GEMM consumes raw bits
                    float o0 = roundtf(fmaxf(acc[i][j][0] + bi0, 0.f));
                    float o1 = roundtf(fmaxf(acc[i][j][1] + bi1, 0.f));
                    float o2 = roundtf(fmaxf(acc[i][j][2] + bi0, 0.f));
                    float o3 = roundtf(fmaxf(acc[i][j][3] + bi1, 0.f));
                    if (r0 < M)
                        *reinterpret_cast<float2*>(uself + (size_t)r0 * HID + cc) = make_float2(o0, o1);
                    if (r1 < M)
                        *reinterpret_cast<float2*>(uself + (size_t)r1 * HID + cc) = make_float2(o2, o3);
                }
            }
        }
    }
    __syncthreads();

    // --- pos head: pos = upos @ Wp2 + bp2 ---
    if (tid < 128) {
        int r = rowBase + tid;
        if (r < M) {
            float p0 = __ldg(bp2), p1 = __ldg(bp2 + 1);
#pragma unroll
            for (int k = 0; k < HID; k++) {
                float v = upos[tid * 65 + k];
                p0 = fmaf(v, __ldg(Wp2 + k * 2), p0);
                p1 = fmaf(v, __ldg(Wp2 + k * 2 + 1), p1);
            }
            pos_out[(size_t)r * 2]     = p0;
            pos_out[(size_t)r * 2 + 1] = p1;
        }
    }
}

// ---------------- single-kernel BatchNorm stats (last-block reduce) ------
__global__ __launch_bounds__(256)
void bn_fused(const float* __restrict__ z,
              const float* __restrict__ gamma, const float* __restrict__ beta)
{
    __shared__ float sh1[4][64], sh2[4][64];
    __shared__ unsigned done;
    const int t = threadIdx.x;
    const int c = t & 63, q = t >> 6;
    const int b = blockIdx.x;

    float s = 0.f, ss = 0.f;
    int r0 = b * 100 + q * 25;
    for (int r = r0; r < r0 + 25; r++) {
        float v = z[(size_t)r * HID + c];
        s += v; ss += v * v;
    }
    sh1[q][c] = s; sh2[q][c] = ss;
    __syncthreads();
    if (q == 0) {
        s  = sh1[0][c] + sh1[1][c] + sh1[2][c] + sh1[3][c];
        ss = sh2[0][c] + sh2[1][c] + sh2[2][c] + sh2[3][c];
        g_part[b * 128 + c]      = s;
        g_part[b * 128 + 64 + c] = ss;
    }
    __threadfence();
    __syncthreads();
    if (t == 0) done = atomicInc(&g_bnctr, 499);
    __syncthreads();
    if (done == 499) {
        float s2 = 0.f, ss2 = 0.f;
        for (int bb = q; bb < 500; bb += 4) {
            s2  += g_part[bb * 128 + c];
            ss2 += g_part[bb * 128 + 64 + c];
        }
        sh1[q][c] = s2; sh2[q][c] = ss2;
        __syncthreads();
        if (q == 0) {
            float S  = sh1[0][c] + sh1[1][c] + sh1[2][c] + sh1[3][c];
            float SS = sh2[0][c] + sh2[1][c] + sh2[2][c] + sh2[3][c];
            float mu = S / (float)NSPOT;
            float var = SS / (float)NSPOT - mu * mu;
            float rstd = rsqrtf(var + BN_EPS);
            float sc = gamma[c] * rstd;
            g_sc[c] = sc;
            g_sh[c] = beta[c] - mu * sc;
        }
    }
}

// ---------------- pre-round B matrices for the big GEMMs -----------------
__global__ __launch_bounds__(256)
void prep_b(const float* __restrict__ Ws2, const float* __restrict__ We2)
{
    int i = blockIdx.x * blockDim.x + threadIdx.x;
    if (i < HID * NGENE) {
        g_wb[i]               = roundtf(Ws2[i]);
        g_wb[HID * NGENE + i] = roundtf(We2[i]);
    }
}

// ---------------- edge aggregation ---------------------------------------
__global__ void scatter_h(const float* __restrict__ h, const int* __restrict__ ei)
{
    long t = (long)blockIdx.x * blockDim.x + threadIdx.x;
    if (t >= (long)NEDGE * 16) return;
    int e = (int)(t >> 4), p = (int)(t & 15);
    int src = __ldg(ei + e);
    int dst = __ldg(ei + NEDGE + e);
    float4 v = *reinterpret_cast<const float4*>(h + (size_t)src * HID + p * 4);
    float* a = g_agg + (size_t)dst * HID + p * 4;
    if (p == 0) atomicAdd(&g_cnt[dst], 1);
    asm volatile("red.global.add.v4.f32 [%0], {%1,%2,%3,%4};"
                 :: "l"(a), "f"(v.x), "f"(v.y), "f"(v.z), "f"(v.w) : "memory");
}

// ---------------- launch ---------------------------------------------------
extern "C" void kernel_launch(void* const* d_in, const int* in_sizes, int n_in,
                              void* d_out, int out_size)
{
    const float* x     = (const float*)d_in[0];
    const int*   ei    = (const int*)  d_in[1];
    const float* W1    = (const float*)d_in[2];
    const float* b1    = (const float*)d_in[3];
    const float* gamma = (const float*)d_in[4];
    const float* beta  = (const float*)d_in[5];
    const float* W2    = (const float*)d_in[6];
    const float* b2    = (const float*)d_in[7];
    const float* Wp1   = (const float*)d_in[8];
    const float* bp1   = (const float*)d_in[9];
    const float* Wp2   = (const float*)d_in[10];
    const float* bp2   = (const float*)d_in[11];
    const float* Ws1   = (const float*)d_in[12];
    const float* bs1   = (const float*)d_in[13];
    const float* Ws2   = (const float*)d_in[14];
    const float* bs2   = (const float*)d_in[15];
    const float* We1   = (const float*)d_in[16];
    const float* be1   = (const float*)d_in[17];
    const float* We2   = (const float*)d_in[18];
    const float* be2   = (const float*)d_in[19];

    float* out = (float*)d_out;
    float* h_out   = out;
    float* pos_out = out + (size_t)NSPOT * HID;
    float* xs_out  = pos_out + (size_t)NSPOT * 2;
    float* xn_out  = xs_out + (size_t)NSPOT * NGENE;

    float* zp;   cudaGetSymbolAddress((void**)&zp, g_z);
    float* usp;  cudaGetSymbolAddress((void**)&usp, g_uself);
    float* aggp; cudaGetSymbolAddress((void**)&aggp, g_agg);
    int*   cntp; cudaGetSymbolAddress((void**)&cntp, g_cnt);
    float* wbp;  cudaGetSymbolAddress((void**)&wbp, g_wb);

    const int MB128 = (NSPOT + 127) / 128;   // 391
    dim3 gN64(1, MB128);
    dim3 gBig((NGENE + 127) / 128, MB128);   // 16 x 391

    constexpr int SMEM_G1  = 2 * (128 * 36 + 32 * 72)  * 4;   // 55296
    constexpr int SMEM_BIG = 2 * (128 * 36 + 32 * 136) * 4;   // 71680
    constexpr int SMEMF    = (128 * 68 + 64 * 72 + 64 * 136) * 4;  // 88064
    cudaFuncSetAttribute((const void*)gemm_db<128, 64, false, true, 1>,
                         cudaFuncAttributeMaxDynamicSharedMemorySize, SMEM_G1);
    cudaFuncSetAttribute((const void*)gemm_db<128, 128, false, false, 2>,
                         cudaFuncAttributeMaxDynamicSharedMemorySize, SMEM_BIG);
    cudaFuncSetAttribute(fused_enc, cudaFuncAttributeMaxDynamicSharedMemorySize, SMEMF);

    // zero agg scratch via memset nodes (not kernel launches)
    cudaMemsetAsync(aggp, 0, (size_t)NSPOT * HID * sizeof(float));
    cudaMemsetAsync(cntp, 0, (size_t)NSPOT * sizeof(int));

    // k1. z = x @ W1 + b1  (K=2000; keeps in-loop cvt — latency-bound anyway)
    gemm_db<128, 64, false, true, 1><<<gN64, 256, SMEM_G1>>>(x, W1, b1, zp,
                                                             NSPOT, HID, NGENE);
    // k2. BN stats -> scale/shift
    bn_fused<<<500, 256>>>(zp, gamma, beta);
    // k3. fused encoder tail: h, pos, u_self (u_self tf32-pre-rounded)
    fused_enc<<<MB128, 256, SMEMF>>>(zp, W2, b2, Wp1, bp1, Ws1, bs1, Wp2, bp2,
                                     h_out, pos_out, usp, NSPOT);
    // k4. neighbor aggregation   <-- ncu capture slot
    {
        long tot = (long)NEDGE * 16;
        scatter_h<<<(int)((tot + 255) / 256), 256>>>(h_out, ei);
    }
    // k5. pre-round Ws2 / We2 into g_wb
    prep_b<<<(HID * NGENE + 255) / 256, 256>>>(Ws2, We2);
    // k6. xs = u_self @ Ws2r + bs2  (no cvt in mainloop)
    gemm_db<128, 128, false, false, 2><<<gBig, 256, SMEM_BIG>>>(usp, wbp, bs2, xs_out,
                                                                NSPOT, NGENE, HID);
    // k7. u_nb = relu(mean(agg) @ We1 + be1) -> g_z (tf32-pre-rounded)
    gemm_tf32<128, 64, 32, true, 2, true><<<gN64, 256>>>(aggp, We1, be1, zp,
                                                         NSPOT, HID, HID);
    // k8. xn = u_nb @ We2r + be2  (no cvt in mainloop)
    gemm_db<128, 128, false, false, 2><<<gBig, 256, SMEM_BIG>>>(zp, wbp + HID * NGENE,
                                                                be2, xn_out,
                                                                NSPOT, NGENE, HID);

    (void)in_sizes; (void)n_in; (void)out_size;
}

// round 11
// speedup vs baseline: 1.4246x; 1.4246x over previous
#include <cuda_runtime.h>
#include <cstdint>

#define NSPOT 50000
#define NGENE 2000
#define HID   64
#define NEDGE 800000
#define BN_EPS 1e-5f

// ---------------- device scratch (no allocation allowed) ----------------
__device__ float g_z[NSPOT * HID];        // raw z, later reused for u_nb (tf32-rounded)
__device__ float g_uself[NSPOT * HID];    // relu(h@Ws1+bs1), tf32-rounded
__device__ float g_agg[NSPOT * HID];      // neighbor raw sums
__device__ int   g_cnt[NSPOT];
__device__ float g_part[500 * 128];
__device__ float g_sc[HID];               // gamma * rstd
__device__ float g_sh[HID];               // beta - mean * gamma * rstd
__device__ unsigned g_bnctr;              // last-block counter (wraps to 0)
__device__ float g_wb[2 * HID * NGENE];   // tf32-rounded Ws2 | We2

// ---------------- tf32 helpers ------------------------------------------
__device__ __forceinline__ uint32_t f2tf(float f) {
    uint32_t r; asm("cvt.rna.tf32.f32 %0, %1;" : "=r"(r) : "f"(f)); return r;
}
__device__ __forceinline__ float roundtf(float f) {
    return __uint_as_float(f2tf(f));
}
__device__ __forceinline__ void mma8(float* c, const uint32_t* a, const uint32_t* b) {
    asm volatile(
        "mma.sync.aligned.m16n8k8.row.col.f32.tf32.tf32.f32 "
        "{%0,%1,%2,%3}, {%4,%5,%6,%7}, {%8,%9}, {%0,%1,%2,%3};"
        : "+f"(c[0]), "+f"(c[1]), "+f"(c[2]), "+f"(c[3])
        : "r"(a[0]), "r"(a[1]), "r"(a[2]), "r"(a[3]), "r"(b[0]), "r"(b[1]));
}
__device__ __forceinline__ void cpa16(uint32_t s, const void* g, bool pred) {
    int sz = pred ? 16 : 0;
    asm volatile("cp.async.cg.shared.global [%0], [%1], 16, %2;"
                 :: "r"(s), "l"(g), "r"(sz));
}

// ============ generic cp.async double-buffered TF32 GEMM ================
// BM=128, BK=32, BN = 64 or 128. C = A@B + bias. zfill handles ragged M/N/K.
// CVT: round f32->tf32 on smem read; false when operands are pre-rounded.
template<int BN, bool RELU, bool CVT>
__global__ __launch_bounds__(256)
void gemm_db(const float* __restrict__ A, const float* __restrict__ B,
             const float* __restrict__ bias, float* __restrict__ C,
             int M, int N, int K)
{
    constexpr int BM = 128, BK = 32;
    constexpr int ASTR = BK + 4;             // 36
    constexpr int BSTR = BN + 8;
    constexpr int BCH  = BN / 4;             // float4 chunks per B row
    constexpr int STAGE = BM * ASTR + BK * BSTR;
    constexpr int WARPS_N = BN / 32;
    constexpr int WARPS_M = 8 / WARPS_N;
    constexpr int WM = BM / WARPS_M;
    constexpr int MT = WM / 16;

    extern __shared__ __align__(16) float dsm[];

    const int tid = threadIdx.x;
    const int lane = tid & 31, wid = tid >> 5;
    const int g = lane >> 2, tg = lane & 3;
    const int rowBase = blockIdx.y * BM;
    const int colBase = blockIdx.x * BN;
    const int mW = (wid / WARPS_N) * WM;
    const int nW = (wid % WARPS_N) * 32;

    float acc[MT][4][4];
#pragma unroll
    for (int i = 0; i < MT; i++)
#pragma unroll
        for (int j = 0; j < 4; j++)
#pragma unroll
            for (int q = 0; q < 4; q++) acc[i][j][q] = 0.f;

    const int KT = (K + BK - 1) / BK;

    auto loadTiles = [&](int buf, int k0) {
        float* Ab = dsm + buf * STAGE;
        float* Bb = Ab + BM * ASTR;
#pragma unroll
        for (int ii = 0; ii < 4; ii++) {                  // A: 1024 float4 chunks
            int i = tid + ii * 256;
            int m = i >> 3, k4 = (i & 7) * 4;
            int r = rowBase + m, gk = k0 + k4;
            cpa16((uint32_t)__cvta_generic_to_shared(Ab + m * ASTR + k4),
                  A + (size_t)r * K + gk, (r < M) && (gk < K));
        }
#pragma unroll
        for (int ii = 0; ii < (BK * BCH) / 256; ii++) {   // B chunks
            int i = tid + ii * 256;
            int kk = i / BCH, n4 = (i % BCH) * 4;
            int gk = k0 + kk, c = colBase + n4;
            cpa16((uint32_t)__cvta_generic_to_shared(Bb + kk * BSTR + n4),
                  B + (size_t)gk * N + c, (gk < K) && (c < N));
        }
    };

    loadTiles(0, 0);
    asm volatile("cp.async.commit_group;");
    int buf = 0;
    for (int kt = 0; kt < KT; kt++) {
        if (kt + 1 < KT) loadTiles(buf ^ 1, (kt + 1) * BK);
        asm volatile("cp.async.commit_group;");
        asm volatile("cp.async.wait_group 1;");
        __syncthreads();
        const float* Ab = dsm + buf * STAGE;
        const float* Bb = Ab + BM * ASTR;
#pragma unroll
        for (int ks = 0; ks < BK / 8; ks++) {
            uint32_t a[MT][4], b[4][2];
#pragma unroll
            for (int i = 0; i < MT; i++) {
                int r0 = mW + i * 16 + g;
                float v0 = Ab[r0 * ASTR + ks * 8 + tg];
                float v1 = Ab[(r0 + 8) * ASTR + ks * 8 + tg];
                float v2 = Ab[r0 * ASTR + ks * 8 + tg + 4];
                float v3 = Ab[(r0 + 8) * ASTR + ks * 8 + tg + 4];
                a[i][0] = CVT ? f2tf(v0) : __float_as_uint(v0);
                a[i][1] = CVT ? f2tf(v1) : __float_as_uint(v1);
                a[i][2] = CVT ? f2tf(v2) : __float_as_uint(v2);
                a[i][3] = CVT ? f2tf(v3) : __float_as_uint(v3);
            }
#pragma unroll
            for (int j = 0; j < 4; j++) {
                float w0 = Bb[(ks * 8 + tg) * BSTR + nW + j * 8 + g];
                float w1 = Bb[(ks * 8 + tg + 4) * BSTR + nW + j * 8 + g];
                b[j][0] = CVT ? f2tf(w0) : __float_as_uint(w0);
                b[j][1] = CVT ? f2tf(w1) : __float_as_uint(w1);
            }
#pragma unroll
            for (int i = 0; i < MT; i++)
#pragma unroll
                for (int j = 0; j < 4; j++)
                    mma8(acc[i][j], a[i], b[j]);
        }
        __syncthreads();
        buf ^= 1;
    }

#pragma unroll
    for (int i = 0; i < MT; i++) {
        int r0 = rowBase + mW + i * 16 + g;
        int r1 = r0 + 8;
#pragma unroll
        for (int j = 0; j < 4; j++) {
            int c = colBase + nW + j * 8 + tg * 2;
            if (c >= N) continue;
            float bi0 = __ldg(bias + c), bi1 = __ldg(bias + c + 1);
            if (r0 < M) {
                float o0 = acc[i][j][0] + bi0, o1 = acc[i][j][1] + bi1;
                if (RELU) { o0 = fmaxf(o0, 0.f); o1 = fmaxf(o1, 0.f); }
                *reinterpret_cast<float2*>(C + (size_t)r0 * N + c) = make_float2(o0, o1);
            }
            if (r1 < M) {
                float o2 = acc[i][j][2] + bi0, o3 = acc[i][j][3] + bi1;
                if (RELU) { o2 = fmaxf(o2, 0.f); o3 = fmaxf(o3, 0.f); }
                *reinterpret_cast<float2*>(C + (size_t)r1 * N + c) = make_float2(o2, o3);
            }
        }
    }
}

// ======== generic TF32 GEMM (single-buffered, static smem) ===============
// AMODE: 0 = none, 2 = per-row 1/cnt on A.  ROUND: tf32-round stored outputs.
template<int BM, int BN, int BK, bool RELU, int AMODE, bool ROUND>
__global__ __launch_bounds__(256)
void gemm_tf32(const float* __restrict__ A, const float* __restrict__ B,
               const float* __restrict__ bias, float* __restrict__ C,
               int M, int N, int K)
{
    constexpr int WARPS_N = BN / 32;
    constexpr int WARPS_M = 8 / WARPS_N;
    constexpr int WM = BM / WARPS_M;
    constexpr int MT = WM / 16;
    constexpr int NT = 4;
    constexpr int ASTR = BK + 4;
    constexpr int BSTR = BN + 8;

    __shared__ __align__(16) uint32_t As[BM * ASTR];
    __shared__ __align__(16) uint32_t Bs[BK * BSTR];

    const int tid = threadIdx.x;
    const int lane = tid & 31, wid = tid >> 5;
    const int g = lane >> 2, tg = lane & 3;
    const int rowBase = blockIdx.y * BM;
    const int colBase = blockIdx.x * BN;
    const int mW = (wid / WARPS_N) * WM;
    const int nW = (wid % WARPS_N) * 32;

    float acc[MT][NT][4];
#pragma unroll
    for (int i = 0; i < MT; i++)
#pragma unroll
        for (int j = 0; j < NT; j++)
#pragma unroll
            for (int q = 0; q < 4; q++) acc[i][j][q] = 0.f;

    for (int k0 = 0; k0 < K; k0 += BK) {
#pragma unroll 2
        for (int i = tid; i < BM * (BK / 4); i += 256) {
            int m = i / (BK / 4), k4 = (i % (BK / 4)) * 4;
            int r = rowBase + m;
            uint4 v = {0u, 0u, 0u, 0u};
            if (r < M) {
                float4 f = *reinterpret_cast<const float4*>(A + (size_t)r * K + k0 + k4);
                if (AMODE == 2) {
                    float inv = 1.0f / fmaxf((float)__ldg(&g_cnt[r]), 1.0f);
                    f.x *= inv; f.y *= inv; f.z *= inv; f.w *= inv;
                }
                v.x = f2tf(f.x); v.y = f2tf(f.y); v.z = f2tf(f.z); v.w = f2tf(f.w);
            }
            *reinterpret_cast<uint4*>(&As[m * ASTR + k4]) = v;
        }
#pragma unroll 2
        for (int i = tid; i < BK * (BN / 4); i += 256) {
            int kk = i / (BN / 4), n4 = (i % (BN / 4)) * 4;
            int c = colBase + n4;
            uint4 v = {0u, 0u, 0u, 0u};
            if (c < N) {
                float4 f = *reinterpret_cast<const float4*>(B + (size_t)(k0 + kk) * N + c);
                v.x = f2tf(f.x); v.y = f2tf(f.y); v.z = f2tf(f.z); v.w = f2tf(f.w);
            }
            *reinterpret_cast<uint4*>(&Bs[kk * BSTR + n4]) = v;
        }
        __syncthreads();
#pragma unroll
        for (int ks = 0; ks < BK / 8; ks++) {
            uint32_t a[MT][4], b[NT][2];
#pragma unroll
            for (int i = 0; i < MT; i++) {
                int r0 = mW + i * 16 + g;
                a[i][0] = As[r0 * ASTR + ks * 8 + tg];
                a[i][1] = As[(r0 + 8) * ASTR + ks * 8 + tg];
                a[i][2] = As[r0 * ASTR + ks * 8 + tg + 4];
                a[i][3] = As[(r0 + 8) * ASTR + ks * 8 + tg + 4];
            }
#pragma unroll
            for (int j = 0; j < NT; j++) {
                b[j][0] = Bs[(ks * 8 + tg) * BSTR + nW + j * 8 + g];
                b[j][1] = Bs[(ks * 8 + tg + 4) * BSTR + nW + j * 8 + g];
            }
#pragma unroll
            for (int i = 0; i < MT; i++)
#pragma unroll
                for (int j = 0; j < NT; j++)
                    mma8(acc[i][j], a[i], b[j]);
        }
        __syncthreads();
    }

#pragma unroll
    for (int i = 0; i < MT; i++) {
        int r0 = rowBase + mW + i * 16 + g;
        int r1 = r0 + 8;
#pragma unroll
        for (int j = 0; j < NT; j++) {
            int c = colBase + nW + j * 8 + tg * 2;
            if (c >= N) continue;
            float bi0 = __ldg(bias + c), bi1 = __ldg(bias + c + 1);
            float o0 = acc[i][j][0] + bi0, o1 = acc[i][j][1] + bi1;
            float o2 = acc[i][j][2] + bi0, o3 = acc[i][j][3] + bi1;
            if (RELU) {
                o0 = fmaxf(o0, 0.f); o1 = fmaxf(o1, 0.f);
                o2 = fmaxf(o2, 0.f); o3 = fmaxf(o3, 0.f);
            }
            if (ROUND) {
                o0 = roundtf(o0); o1 = roundtf(o1);
                o2 = roundtf(o2); o3 = roundtf(o3);
            }
            if (r0 < M)
                *reinterpret_cast<float2*>(C + (size_t)r0 * N + c) = make_float2(o0, o1);
            if (r1 < M)
                *reinterpret_cast<float2*>(C + (size_t)r1 * N + c) = make_float2(o2, o3);
        }
    }
}

// ======== fused encoder tail: BNReLU(z)@W2 -> h ; heads ; pos ============
__global__ __launch_bounds__(256)
void fused_enc(const float* __restrict__ z,
               const float* __restrict__ W2,  const float* __restrict__ b2,
               const float* __restrict__ Wp1, const float* __restrict__ bp1,
               const float* __restrict__ Ws1, const float* __restrict__ bs1,
               const float* __restrict__ Wp2, const float* __restrict__ bp2,
               float* __restrict__ h_out, float* __restrict__ pos_out,
               float* __restrict__ uself, int M)
{
    extern __shared__ __align__(16) uint32_t fsm[];
    uint32_t* Zs  = fsm;                  // 128 x 68 (A layout, tf32)
    uint32_t* W2s = Zs + 128 * 68;        // 64 x 72  (B layout)
    uint32_t* W13 = W2s + 64 * 72;        // 64 x 136 (B layout: Wp1|Ws1)
    float* upos = reinterpret_cast<float*>(W13);   // reuse: 128 x 65

    const int tid = threadIdx.x;
    const int lane = tid & 31, wid = tid >> 5;
    const int g = lane >> 2, tg = lane & 3;
    const int rowBase = blockIdx.x * 128;

#pragma unroll
    for (int ii = 0; ii < 8; ii++) {
        int i = tid + ii * 256;
        int m = i >> 4, k4 = (i & 15) * 4;
        int r = rowBase + m;
        uint4 v = {0u, 0u, 0u, 0u};
        if (r < M) {
            float4 f = *reinterpret_cast<const float4*>(z + (size_t)r * HID + k4);
            f.x = fmaxf(fmaf(f.x, g_sc[k4+0], g_sh[k4+0]), 0.f);
            f.y = fmaxf(fmaf(f.y, g_sc[k4+1], g_sh[k4+1]), 0.f);
            f.z = fmaxf(fmaf(f.z, g_sc[k4+2], g_sh[k4+2]), 0.f);
            f.w = fmaxf(fmaf(f.w, g_sc[k4+3], g_sh[k4+3]), 0.f);
            v.x = f2tf(f.x); v.y = f2tf(f.y); v.z = f2tf(f.z); v.w = f2tf(f.w);
        }
        *reinterpret_cast<uint4*>(&Zs[m * 68 + k4]) = v;
    }
#pragma unroll
    for (int ii = 0; ii < 4; ii++) {
        int i = tid + ii * 256;
        int kk = i >> 4, n4 = (i & 15) * 4;
        float4 f = *reinterpret_cast<const float4*>(W2 + kk * HID + n4);
        uint4 v; v.x = f2tf(f.x); v.y = f2tf(f.y); v.z = f2tf(f.z); v.w = f2tf(f.w);
        *reinterpret_cast<uint4*>(&W2s[kk * 72 + n4]) = v;
    }
#pragma unroll
    for (int ii = 0; ii < 8; ii++) {
        int i = tid + ii * 256;
        int kk = i >> 5, n4 = (i & 31) * 4;
        const float* src = (n4 < 64) ? (Wp1 + kk * HID + n4) : (Ws1 + kk * HID + n4 - 64);
        float4 f = *reinterpret_cast<const float4*>(src);
        uint4 v; v.x = f2tf(f.x); v.y = f2tf(f.y); v.z = f2tf(f.z); v.w = f2tf(f.w);
        *reinterpret_cast<uint4*>(&W13[kk * 136 + n4]) = v;
    }
    __syncthreads();

    // --- stage 1: h = Zs @ W2 + b2 ---
    {
        const int mW = (wid >> 1) * 32;
        const int nW = (wid & 1) * 32;
        float acc[2][4][4];
#pragma unroll
        for (int i = 0; i < 2; i++)
#pragma unroll
            for (int j = 0; j < 4; j++)
#pragma unroll
                for (int q = 0; q < 4; q++) acc[i][j][q] = 0.f;
#pragma unroll
        for (int ks = 0; ks < 8; ks++) {
            uint32_t a[2][4], b[4][2];
#pragma unroll
            for (int i = 0; i < 2; i++) {
                int r0 = mW + i * 16 + g;
                a[i][0] = Zs[r0 * 68 + ks * 8 + tg];
                a[i][1] = Zs[(r0 + 8) * 68 + ks * 8 + tg];
                a[i][2] = Zs[r0 * 68 + ks * 8 + tg + 4];
                a[i][3] = Zs[(r0 + 8) * 68 + ks * 8 + tg + 4];
            }
#pragma unroll
            for (int j = 0; j < 4; j++) {
                b[j][0] = W2s[(ks * 8 + tg) * 72 + nW + j * 8 + g];
                b[j][1] = W2s[(ks * 8 + tg + 4) * 72 + nW + j * 8 + g];
            }
#pragma unroll
            for (int i = 0; i < 2; i++)
#pragma unroll
                for (int j = 0; j < 4; j++)
                    mma8(acc[i][j], a[i], b[j]);
        }
        __syncthreads();
#pragma unroll
        for (int i = 0; i < 2; i++) {
            int lr0 = mW + i * 16 + g, lr1 = lr0 + 8;
            int r0 = rowBase + lr0, r1 = rowBase + lr1;
#pragma unroll
            for (int j = 0; j < 4; j++) {
                int c = nW + j * 8 + tg * 2;
                float bi0 = __ldg(b2 + c), bi1 = __ldg(b2 + c + 1);
                float h0 = acc[i][j][0] + bi0, h1 = acc[i][j][1] + bi1;
                float h2 = acc[i][j][2] + bi0, h3 = acc[i][j][3] + bi1;
                Zs[lr0 * 68 + c] = f2tf(h0); Zs[lr0 * 68 + c + 1] = f2tf(h1);
                Zs[lr1 * 68 + c] = f2tf(h2); Zs[lr1 * 68 + c + 1] = f2tf(h3);
                if (r0 < M)
                    *reinterpret_cast<float2*>(h_out + (size_t)r0 * HID + c) = make_float2(h0, h1);
                if (r1 < M)
                    *reinterpret_cast<float2*>(h_out + (size_t)r1 * HID + c) = make_float2(h2, h3);
            }
        }
    }
    __syncthreads();

    // --- stage 2: [u_pos | u_self] = h @ [Wp1|Ws1] ---
    {
        const int mW = (wid >> 2) * 64;
        const int nW = (wid & 3) * 32;
        float acc[4][4][4];
#pragma unroll
        for (int i = 0; i < 4; i++)
#pragma unroll
            for (int j = 0; j < 4; j++)
#pragma unroll
                for (int q = 0; q < 4; q++) acc[i][j][q] = 0.f;
#pragma unroll
        for (int ks = 0; ks < 8; ks++) {
            uint32_t a[4][4], b[4][2];
#pragma unroll
            for (int i = 0; i < 4; i++) {
                int r0 = mW + i * 16 + g;
                a[i][0] = Zs[r0 * 68 + ks * 8 + tg];
                a[i][1] = Zs[(r0 + 8) * 68 + ks * 8 + tg];
                a[i][2] = Zs[r0 * 68 + ks * 8 + tg + 4];
                a[i][3] = Zs[(r0 + 8) * 68 + ks * 8 + tg + 4];
            }
#pragma unroll
            for (int j = 0; j < 4; j++) {
                b[j][0] = W13[(ks * 8 + tg) * 136 + nW + j * 8 + g];
                b[j][1] = W13[(ks * 8 + tg + 4) * 136 + nW + j * 8 + g];
            }
#pragma unroll
            for (int i = 0; i < 4; i++)
#pragma unroll
                for (int j = 0; j < 4; j++)
                    mma8(acc[i][j], a[i], b[j]);
        }
        __syncthreads();
#pragma unroll
        for (int i = 0; i < 4; i++) {
            int lr0 = mW + i * 16 + g, lr1 = lr0 + 8;
            int r0 = rowBase + lr0, r1 = rowBase + lr1;
#pragma unroll
            for (int j = 0; j < 4; j++) {
                int c = nW + j * 8 + tg * 2;
                if (c < 64) {
                    float bi0 = __ldg(bp1 + c), bi1 = __ldg(bp1 + c + 1);
                    upos[lr0 * 65 + c]     = fmaxf(acc[i][j][0] + bi0, 0.f);
                    upos[lr0 * 65 + c + 1] = fmaxf(acc[i][j][1] + bi1, 0.f);
                    upos[lr1 * 65 + c]     = fmaxf(acc[i][j][2] + bi0, 0.f);
                    upos[lr1 * 65 + c + 1] = fmaxf(acc[i][j][3] + bi1, 0.f);
                } else {
                    int cc = c - 64;
                    float bi0 = __ldg(bs1 + cc), bi1 = __ldg(bs1 + cc + 1);
                    // tf32-rounded at write: xs GEMM consumes raw bits
                    float o0 = roundtf(fmaxf(acc[i][j][0] + bi0, 0.f));
                    float o1 = roundtf(fmaxf(acc[i][j][1] + bi1, 0.f));
                    float o2 = roundtf(fmaxf(acc[i][j][2] + bi0, 0.f));
                    float o3 = roundtf(fmaxf(acc[i][j][3] + bi1, 0.f));
                    if (r0 < M)
                        *reinterpret_cast<float2*>(uself + (size_t)r0 * HID + cc) = make_float2(o0, o1);
                    if (r1 < M)
                        *reinterpret_cast<float2*>(uself + (size_t)r1 * HID + cc) = make_float2(o2, o3);
                }
            }
        }
    }
    __syncthreads();

    // --- pos head: pos = upos @ Wp2 + bp2 ---
    if (tid < 128) {
        int r = rowBase + tid;
        if (r < M) {
            float p0 = __ldg(bp2), p1 = __ldg(bp2 + 1);
#pragma unroll
            for (int k = 0; k < HID; k++) {
                float v = upos[tid * 65 + k];
                p0 = fmaf(v, __ldg(Wp2 + k * 2), p0);
                p1 = fmaf(v, __ldg(Wp2 + k * 2 + 1), p1);
            }
            pos_out[(size_t)r * 2]     = p0;
            pos_out[(size_t)r * 2 + 1] = p1;
        }
    }
}

// ---------------- single-kernel BatchNorm stats (last-block reduce) ------
__global__ __launch_bounds__(256)
void bn_fused(const float* __restrict__ z,
              const float* __restrict__ gamma, const float* __restrict__ beta)
{
    __shared__ float sh1[4][64], sh2[4][64];
    __shared__ unsigned done;
    const int t = threadIdx.x;
    const int c = t & 63, q = t >> 6;
    const int b = blockIdx.x;

    float s = 0.f, ss = 0.f;
    int r0 = b * 100 + q * 25;
    for (int r = r0; r < r0 + 25; r++) {
        float v = z[(size_t)r * HID + c];
        s += v; ss += v * v;
    }
    sh1[q][c] = s; sh2[q][c] = ss;
    __syncthreads();
    if (q == 0) {
        s  = sh1[0][c] + sh1[1][c] + sh1[2][c] + sh1[3][c];
        ss = sh2[0][c] + sh2[1][c] + sh2[2][c] + sh2[3][c];
        g_part[b * 128 + c]      = s;
        g_part[b * 128 + 64 + c] = ss;
    }
    __threadfence();
    __syncthreads();
    if (t == 0) done = atomicInc(&g_bnctr, 499);
    __syncthreads();
    if (done == 499) {
        float s2 = 0.f, ss2 = 0.f;
        for (int bb = q; bb < 500; bb += 4) {
            s2  += g_part[bb * 128 + c];
            ss2 += g_part[bb * 128 + 64 + c];
        }
        sh1[q][c] = s2; sh2[q][c] = ss2;
        __syncthreads();
        if (q == 0) {
            float S  = sh1[0][c] + sh1[1][c] + sh1[2][c] + sh1[3][c];
            float SS = sh2[0][c] + sh2[1][c] + sh2[2][c] + sh2[3][c];
            float mu = S / (float)NSPOT;
            float var = SS / (float)NSPOT - mu * mu;
            float rstd = rsqrtf(var + BN_EPS);
            float sc = gamma[c] * rstd;
            g_sc[c] = sc;
            g_sh[c] = beta[c] - mu * sc;
        }
    }
}

// ---------------- pre-round B matrices for the big GEMMs -----------------
__global__ __launch_bounds__(256)
void prep_b(const float* __restrict__ Ws2, const float* __restrict__ We2)
{
    int i = blockIdx.x * blockDim.x + threadIdx.x;
    if (i < HID * NGENE) {
        g_wb[i]               = roundtf(Ws2[i]);
        g_wb[HID * NGENE + i] = roundtf(We2[i]);
    }
}

// ---------------- edge aggregation ---------------------------------------
__global__ void scatter_h(const float* __restrict__ h, const int* __restrict__ ei)
{
    long t = (long)blockIdx.x * blockDim.x + threadIdx.x;
    if (t >= (long)NEDGE * 16) return;
    int e = (int)(t >> 4), p = (int)(t & 15);
    int src = __ldg(ei + e);
    int dst = __ldg(ei + NEDGE + e);
    float4 v = *reinterpret_cast<const float4*>(h + (size_t)src * HID + p * 4);
    float* a = g_agg + (size_t)dst * HID + p * 4;
    if (p == 0) atomicAdd(&g_cnt[dst], 1);
    asm volatile("red.global.add.v4.f32 [%0], {%1,%2,%3,%4};"
                 :: "l"(a), "f"(v.x), "f"(v.y), "f"(v.z), "f"(v.w) : "memory");
}

// ---------------- launch ---------------------------------------------------
extern "C" void kernel_launch(void* const* d_in, const int* in_sizes, int n_in,
                              void* d_out, int out_size)
{
    const float* x     = (const float*)d_in[0];
    const int*   ei    = (const int*)  d_in[1];
    const float* W1    = (const float*)d_in[2];
    const float* b1    = (const float*)d_in[3];
    const float* gamma = (const float*)d_in[4];
    const float* beta  = (const float*)d_in[5];
    const float* W2    = (const float*)d_in[6];
    const float* b2    = (const float*)d_in[7];
    const float* Wp1   = (const float*)d_in[8];
    const float* bp1   = (const float*)d_in[9];
    const float* Wp2   = (const float*)d_in[10];
    const float* bp2   = (const float*)d_in[11];
    const float* Ws1   = (const float*)d_in[12];
    const float* bs1   = (const float*)d_in[13];
    const float* Ws2   = (const float*)d_in[14];
    const float* bs2   = (const float*)d_in[15];
    const float* We1   = (const float*)d_in[16];
    const float* be1   = (const float*)d_in[17];
    const float* We2   = (const float*)d_in[18];
    const float* be2   = (const float*)d_in[19];

    float* out = (float*)d_out;
    float* h_out   = out;
    float* pos_out = out + (size_t)NSPOT * HID;
    float* xs_out  = pos_out + (size_t)NSPOT * 2;
    float* xn_out  = xs_out + (size_t)NSPOT * NGENE;

    float* zp;   cudaGetSymbolAddress((void**)&zp, g_z);
    float* usp;  cudaGetSymbolAddress((void**)&usp, g_uself);
    float* aggp; cudaGetSymbolAddress((void**)&aggp, g_agg);
    int*   cntp; cudaGetSymbolAddress((void**)&cntp, g_cnt);
    float* wbp;  cudaGetSymbolAddress((void**)&wbp, g_wb);

    const int MB128 = (NSPOT + 127) / 128;   // 391
    dim3 gN64(1, MB128);
    dim3 gBig((NGENE + 127) / 128, MB128);   // 16 x 391

    constexpr int SMEM_G1  = 2 * (128 * 36 + 32 * 72)  * 4;   // 55296
    constexpr int SMEM_BIG = 2 * (128 * 36 + 32 * 136) * 4;   // 71680
    constexpr int SMEMF    = (128 * 68 + 64 * 72 + 64 * 136) * 4;  // 88064
    cudaFuncSetAttribute((const void*)gemm_db<64, false, true>,
                         cudaFuncAttributeMaxDynamicSharedMemorySize, SMEM_G1);
    cudaFuncSetAttribute((const void*)gemm_db<128, false, false>,
                         cudaFuncAttributeMaxDynamicSharedMemorySize, SMEM_BIG);
    cudaFuncSetAttribute(fused_enc, cudaFuncAttributeMaxDynamicSharedMemorySize, SMEMF);

    // zero agg scratch via memset nodes (not kernel launches)
    cudaMemsetAsync(aggp, 0, (size_t)NSPOT * HID * sizeof(float));
    cudaMemsetAsync(cntp, 0, (size_t)NSPOT * sizeof(int));

    // k1. pre-round Ws2 / We2 (depends only on inputs)
    prep_b<<<(HID * NGENE + 255) / 256, 256>>>(Ws2, We2);
    // k2. z = x @ W1 + b1  (K=2000; keeps in-loop cvt)
    gemm_db<64, false, true><<<gN64, 256, SMEM_G1>>>(x, W1, b1, zp, NSPOT, HID, NGENE);
    // k3. BN stats -> scale/shift
    bn_fused<<<500, 256>>>(zp, gamma, beta);
    // k4. fused encoder tail: h, pos, u_self   <-- ncu capture slot
    fused_enc<<<MB128, 256, SMEMF>>>(zp, W2, b2, Wp1, bp1, Ws1, bs1, Wp2, bp2,
                                     h_out, pos_out, usp, NSPOT);
    // k5. xs = u_self @ Ws2r + bs2  (no cvt in mainloop, no reg cap)
    gemm_db<128, false, false><<<gBig, 256, SMEM_BIG>>>(usp, wbp, bs2, xs_out,
                                                        NSPOT, NGENE, HID);
    // k6. neighbor aggregation
    {
        long tot = (long)NEDGE * 16;
        scatter_h<<<(int)((tot + 255) / 256), 256>>>(h_out, ei);
    }
    // k7. u_nb = relu(mean(agg) @ We1 + be1) -> g_z (tf32-pre-rounded)
    gemm_tf32<128, 64, 32, true, 2, true><<<gN64, 256>>>(aggp, We1, be1, zp,
                                                         NSPOT, HID, HID);
    // k8. xn = u_nb @ We2r + be2  (no cvt in mainloop)
    gemm_db<128, false, false><<<gBig, 256, SMEM_BIG>>>(zp, wbp + HID * NGENE,
                                                        be2, xn_out,
                                                        NSPOT, NGENE, HID);

    (void)in_sizes; (void)n_in; (void)out_size;
}

// round 12
// speedup vs baseline: 1.4540x; 1.0206x over previous
#include <cuda_runtime.h>
#include <cstdint>

#define NSPOT 50000
#define NGENE 2000
#define HID   64
#define NEDGE 800000
#define BN_EPS 1e-5f

// ---------------- device scratch (no allocation allowed) ----------------
__device__ float g_z[NSPOT * HID];        // raw z, later reused for u_nb (tf32-rounded)
__device__ float g_uself[NSPOT * HID];    // relu(h@Ws1+bs1), tf32-rounded
__device__ float g_agg[NSPOT * HID];      // neighbor raw sums
__device__ int   g_cnt[NSPOT];
__device__ float g_part[500 * 128];
__device__ float g_sc[HID];               // gamma * rstd
__device__ float g_sh[HID];               // beta - mean * gamma * rstd
__device__ unsigned g_bnctr;              // last-block counter (wraps to 0)
__device__ float g_wb[2 * HID * NGENE];   // tf32-rounded Ws2 | We2

// ---------------- tf32 helpers ------------------------------------------
__device__ __forceinline__ uint32_t f2tf(float f) {
    uint32_t r; asm("cvt.rna.tf32.f32 %0, %1;" : "=r"(r) : "f"(f)); return r;
}
__device__ __forceinline__ float roundtf(float f) {
    return __uint_as_float(f2tf(f));
}
__device__ __forceinline__ void mma8(float* c, const uint32_t* a, const uint32_t* b) {
    asm volatile(
        "mma.sync.aligned.m16n8k8.row.col.f32.tf32.tf32.f32 "
        "{%0,%1,%2,%3}, {%4,%5,%6,%7}, {%8,%9}, {%0,%1,%2,%3};"
        : "+f"(c[0]), "+f"(c[1]), "+f"(c[2]), "+f"(c[3])
        : "r"(a[0]), "r"(a[1]), "r"(a[2]), "r"(a[3]), "r"(b[0]), "r"(b[1]));
}
__device__ __forceinline__ void cpa16(uint32_t s, const void* g, bool pred) {
    int sz = pred ? 16 : 0;
    asm volatile("cp.async.cg.shared.global [%0], [%1], 16, %2;"
                 :: "r"(s), "l"(g), "r"(sz));
}
__device__ __forceinline__ void stg2_cs(float* p, float a, float b) {
    asm volatile("st.global.cs.v2.f32 [%0], {%1,%2};" :: "l"(p), "f"(a), "f"(b) : "memory");
}

// ============ generic cp.async double-buffered TF32 GEMM ================
// BM=128, BK=32, BN = 64 or 128. C = A@B + bias. zfill handles ragged M/N/K.
// CVT: round f32->tf32 on smem read (false when operands pre-rounded).
// CS: streaming (evict-first) stores for C.
template<int BN, bool RELU, bool CVT, bool CS>
__global__ __launch_bounds__(256)
void gemm_db(const float* __restrict__ A, const float* __restrict__ B,
             const float* __restrict__ bias, float* __restrict__ C,
             int M, int N, int K)
{
    constexpr int BM = 128, BK = 32;
    constexpr int ASTR = BK + 4;             // 36
    constexpr int BSTR = BN + 8;
    constexpr int BCH  = BN / 4;             // float4 chunks per B row
    constexpr int STAGE = BM * ASTR + BK * BSTR;
    constexpr int WARPS_N = BN / 32;
    constexpr int WARPS_M = 8 / WARPS_N;
    constexpr int WM = BM / WARPS_M;
    constexpr int MT = WM / 16;

    extern __shared__ __align__(16) float dsm[];

    const int tid = threadIdx.x;
    const int lane = tid & 31, wid = tid >> 5;
    const int g = lane >> 2, tg = lane & 3;
    const int rowBase = blockIdx.y * BM;
    const int colBase = blockIdx.x * BN;
    const int mW = (wid / WARPS_N) * WM;
    const int nW = (wid % WARPS_N) * 32;

    float acc[MT][4][4];
#pragma unroll
    for (int i = 0; i < MT; i++)
#pragma unroll
        for (int j = 0; j < 4; j++)
#pragma unroll
            for (int q = 0; q < 4; q++) acc[i][j][q] = 0.f;

    const int KT = (K + BK - 1) / BK;

    auto loadTiles = [&](int buf, int k0) {
        float* Ab = dsm + buf * STAGE;
        float* Bb = Ab + BM * ASTR;
#pragma unroll
        for (int ii = 0; ii < 4; ii++) {                  // A: 1024 float4 chunks
            int i = tid + ii * 256;
            int m = i >> 3, k4 = (i & 7) * 4;
            int r = rowBase + m, gk = k0 + k4;
            cpa16((uint32_t)__cvta_generic_to_shared(Ab + m * ASTR + k4),
                  A + (size_t)r * K + gk, (r < M) && (gk < K));
        }
#pragma unroll
        for (int ii = 0; ii < (BK * BCH) / 256; ii++) {   // B chunks
            int i = tid + ii * 256;
            int kk = i / BCH, n4 = (i % BCH) * 4;
            int gk = k0 + kk, c = colBase + n4;
            cpa16((uint32_t)__cvta_generic_to_shared(Bb + kk * BSTR + n4),
                  B + (size_t)gk * N + c, (gk < K) && (c < N));
        }
    };

    loadTiles(0, 0);
    asm volatile("cp.async.commit_group;");
    int buf = 0;
    for (int kt = 0; kt < KT; kt++) {
        if (kt + 1 < KT) loadTiles(buf ^ 1, (kt + 1) * BK);
        asm volatile("cp.async.commit_group;");
        asm volatile("cp.async.wait_group 1;");
        __syncthreads();
        const float* Ab = dsm + buf * STAGE;
        const float* Bb = Ab + BM * ASTR;
#pragma unroll
        for (int ks = 0; ks < BK / 8; ks++) {
            uint32_t a[MT][4], b[4][2];
#pragma unroll
            for (int i = 0; i < MT; i++) {
                int r0 = mW + i * 16 + g;
                float v0 = Ab[r0 * ASTR + ks * 8 + tg];
                float v1 = Ab[(r0 + 8) * ASTR + ks * 8 + tg];
                float v2 = Ab[r0 * ASTR + ks * 8 + tg + 4];
                float v3 = Ab[(r0 + 8) * ASTR + ks * 8 + tg + 4];
                a[i][0] = CVT ? f2tf(v0) : __float_as_uint(v0);
                a[i][1] = CVT ? f2tf(v1) : __float_as_uint(v1);
                a[i][2] = CVT ? f2tf(v2) : __float_as_uint(v2);
                a[i][3] = CVT ? f2tf(v3) : __float_as_uint(v3);
            }
#pragma unroll
            for (int j = 0; j < 4; j++) {
                float w0 = Bb[(ks * 8 + tg) * BSTR + nW + j * 8 + g];
                float w1 = Bb[(ks * 8 + tg + 4) * BSTR + nW + j * 8 + g];
                b[j][0] = CVT ? f2tf(w0) : __float_as_uint(w0);
                b[j][1] = CVT ? f2tf(w1) : __float_as_uint(w1);
            }
#pragma unroll
            for (int i = 0; i < MT; i++)
#pragma unroll
                for (int j = 0; j < 4; j++)
                    mma8(acc[i][j], a[i], b[j]);
        }
        __syncthreads();
        buf ^= 1;
    }

#pragma unroll
    for (int i = 0; i < MT; i++) {
        int r0 = rowBase + mW + i * 16 + g;
        int r1 = r0 + 8;
#pragma unroll
        for (int j = 0; j < 4; j++) {
            int c = colBase + nW + j * 8 + tg * 2;
            if (c >= N) continue;
            float bi0 = __ldg(bias + c), bi1 = __ldg(bias + c + 1);
            if (r0 < M) {
                float o0 = acc[i][j][0] + bi0, o1 = acc[i][j][1] + bi1;
                if (RELU) { o0 = fmaxf(o0, 0.f); o1 = fmaxf(o1, 0.f); }
                if (CS) stg2_cs(C + (size_t)r0 * N + c, o0, o1);
                else *reinterpret_cast<float2*>(C + (size_t)r0 * N + c) = make_float2(o0, o1);
            }
            if (r1 < M) {
                float o2 = acc[i][j][2] + bi0, o3 = acc[i][j][3] + bi1;
                if (RELU) { o2 = fmaxf(o2, 0.f); o3 = fmaxf(o3, 0.f); }
                if (CS) stg2_cs(C + (size_t)r1 * N + c, o2, o3);
                else *reinterpret_cast<float2*>(C + (size_t)r1 * N + c) = make_float2(o2, o3);
            }
        }
    }
}

// ======== generic TF32 GEMM (single-buffered, static smem) ===============
// AMODE: 0 = none, 2 = per-row 1/cnt on A.  ROUND: tf32-round stored outputs.
template<int BM, int BN, int BK, bool RELU, int AMODE, bool ROUND>
__global__ __launch_bounds__(256)
void gemm_tf32(const float* __restrict__ A, const float* __restrict__ B,
               const float* __restrict__ bias, float* __restrict__ C,
               int M, int N, int K)
{
    constexpr int WARPS_N = BN / 32;
    constexpr int WARPS_M = 8 / WARPS_N;
    constexpr int WM = BM / WARPS_M;
    constexpr int MT = WM / 16;
    constexpr int NT = 4;
    constexpr int ASTR = BK + 4;
    constexpr int BSTR = BN + 8;

    __shared__ __align__(16) uint32_t As[BM * ASTR];
    __shared__ __align__(16) uint32_t Bs[BK * BSTR];

    const int tid = threadIdx.x;
    const int lane = tid & 31, wid = tid >> 5;
    const int g = lane >> 2, tg = lane & 3;
    const int rowBase = blockIdx.y * BM;
    const int colBase = blockIdx.x * BN;
    const int mW = (wid / WARPS_N) * WM;
    const int nW = (wid % WARPS_N) * 32;

    float acc[MT][NT][4];
#pragma unroll
    for (int i = 0; i < MT; i++)
#pragma unroll
        for (int j = 0; j < NT; j++)
#pragma unroll
            for (int q = 0; q < 4; q++) acc[i][j][q] = 0.f;

    for (int k0 = 0; k0 < K; k0 += BK) {
#pragma unroll 2
        for (int i = tid; i < BM * (BK / 4); i += 256) {
            int m = i / (BK / 4), k4 = (i % (BK / 4)) * 4;
            int r = rowBase + m;
            uint4 v = {0u, 0u, 0u, 0u};
            if (r < M) {
                float4 f = *reinterpret_cast<const float4*>(A + (size_t)r * K + k0 + k4);
                if (AMODE == 2) {
                    float inv = 1.0f / fmaxf((float)__ldg(&g_cnt[r]), 1.0f);
                    f.x *= inv; f.y *= inv; f.z *= inv; f.w *= inv;
                }
                v.x = f2tf(f.x); v.y = f2tf(f.y); v.z = f2tf(f.z); v.w = f2tf(f.w);
            }
            *reinterpret_cast<uint4*>(&As[m * ASTR + k4]) = v;
        }
#pragma unroll 2
        for (int i = tid; i < BK * (BN / 4); i += 256) {
            int kk = i / (BN / 4), n4 = (i % (BN / 4)) * 4;
            int c = colBase + n4;
            uint4 v = {0u, 0u, 0u, 0u};
            if (c < N) {
                float4 f = *reinterpret_cast<const float4*>(B + (size_t)(k0 + kk) * N + c);
                v.x = f2tf(f.x); v.y = f2tf(f.y); v.z = f2tf(f.z); v.w = f2tf(f.w);
            }
            *reinterpret_cast<uint4*>(&Bs[kk * BSTR + n4]) = v;
        }
        __syncthreads();
#pragma unroll
        for (int ks = 0; ks < BK / 8; ks++) {
            uint32_t a[MT][4], b[NT][2];
#pragma unroll
            for (int i = 0; i < MT; i++) {
                int r0 = mW + i * 16 + g;
                a[i][0] = As[r0 * ASTR + ks * 8 + tg];
                a[i][1] = As[(r0 + 8) * ASTR + ks * 8 + tg];
                a[i][2] = As[r0 * ASTR + ks * 8 + tg + 4];
                a[i][3] = As[(r0 + 8) * ASTR + ks * 8 + tg + 4];
            }
#pragma unroll
            for (int j = 0; j < NT; j++) {
                b[j][0] = Bs[(ks * 8 + tg) * BSTR + nW + j * 8 + g];
                b[j][1] = Bs[(ks * 8 + tg + 4) * BSTR + nW + j * 8 + g];
            }
#pragma unroll
            for (int i = 0; i < MT; i++)
#pragma unroll
                for (int j = 0; j < NT; j++)
                    mma8(acc[i][j], a[i], b[j]);
        }
        __syncthreads();
    }

#pragma unroll
    for (int i = 0; i < MT; i++) {
        int r0 = rowBase + mW + i * 16 + g;
        int r1 = r0 + 8;
#pragma unroll
        for (int j = 0; j < NT; j++) {
            int c = colBase + nW + j * 8 + tg * 2;
            if (c >= N) continue;
            float bi0 = __ldg(bias + c), bi1 = __ldg(bias + c + 1);
            float o0 = acc[i][j][0] + bi0, o1 = acc[i][j][1] + bi1;
            float o2 = acc[i][j][2] + bi0, o3 = acc[i][j][3] + bi1;
            if (RELU) {
                o0 = fmaxf(o0, 0.f); o1 = fmaxf(o1, 0.f);
                o2 = fmaxf(o2, 0.f); o3 = fmaxf(o3, 0.f);
            }
            if (ROUND) {
                o0 = roundtf(o0); o1 = roundtf(o1);
                o2 = roundtf(o2); o3 = roundtf(o3);
            }
            if (r0 < M)
                *reinterpret_cast<float2*>(C + (size_t)r0 * N + c) = make_float2(o0, o1);
            if (r1 < M)
                *reinterpret_cast<float2*>(C + (size_t)r1 * N + c) = make_float2(o2, o3);
        }
    }
}

// ======== fused encoder tail: BNReLU(z)@W2 -> h ; heads ; pos ============
__global__ __launch_bounds__(256)
void fused_enc(const float* __restrict__ z,
               const float* __restrict__ W2,  const float* __restrict__ b2,
               const float* __restrict__ Wp1, const float* __restrict__ bp1,
               const float* __restrict__ Ws1, const float* __restrict__ bs1,
               const float* __restrict__ Wp2, const float* __restrict__ bp2,
               float* __restrict__ h_out, float* __restrict__ pos_out,
               float* __restrict__ uself, int M)
{
    extern __shared__ __align__(16) uint32_t fsm[];
    uint32_t* Zs  = fsm;                  // 128 x 68 (A layout, tf32)
    uint32_t* W2s = Zs + 128 * 68;        // 64 x 72  (B layout)
    uint32_t* W13 = W2s + 64 * 72;        // 64 x 136 (B layout: Wp1|Ws1)
    float* upos = reinterpret_cast<float*>(W13);   // reuse: 128 x 65

    const int tid = threadIdx.x;
    const int lane = tid & 31, wid = tid >> 5;
    const int g = lane >> 2, tg = lane & 3;
    const int rowBase = blockIdx.x * 128;

#pragma unroll
    for (int ii = 0; ii < 8; ii++) {
        int i = tid + ii * 256;
        int m = i >> 4, k4 = (i & 15) * 4;
        int r = rowBase + m;
        uint4 v = {0u, 0u, 0u, 0u};
        if (r < M) {
            float4 f = *reinterpret_cast<const float4*>(z + (size_t)r * HID + k4);
            f.x = fmaxf(fmaf(f.x, g_sc[k4+0], g_sh[k4+0]), 0.f);
            f.y = fmaxf(fmaf(f.y, g_sc[k4+1], g_sh[k4+1]), 0.f);
            f.z = fmaxf(fmaf(f.z, g_sc[k4+2], g_sh[k4+2]), 0.f);
            f.w = fmaxf(fmaf(f.w, g_sc[k4+3], g_sh[k4+3]), 0.f);
            v.x = f2tf(f.x); v.y = f2tf(f.y); v.z = f2tf(f.z); v.w = f2tf(f.w);
        }
        *reinterpret_cast<uint4*>(&Zs[m * 68 + k4]) = v;
    }
#pragma unroll
    for (int ii = 0; ii < 4; ii++) {
        int i = tid + ii * 256;
        int kk = i >> 4, n4 = (i & 15) * 4;
        float4 f = *reinterpret_cast<const float4*>(W2 + kk * HID + n4);
        uint4 v; v.x = f2tf(f.x); v.y = f2tf(f.y); v.z = f2tf(f.z); v.w = f2tf(f.w);
        *reinterpret_cast<uint4*>(&W2s[kk * 72 + n4]) = v;
    }
#pragma unroll
    for (int ii = 0; ii < 8; ii++) {
        int i = tid + ii * 256;
        int kk = i >> 5, n4 = (i & 31) * 4;
        const float* src = (n4 < 64) ? (Wp1 + kk * HID + n4) : (Ws1 + kk * HID + n4 - 64);
        float4 f = *reinterpret_cast<const float4*>(src);
        uint4 v; v.x = f2tf(f.x); v.y = f2tf(f.y); v.z = f2tf(f.z); v.w = f2tf(f.w);
        *reinterpret_cast<uint4*>(&W13[kk * 136 + n4]) = v;
    }
    __syncthreads();

    // --- stage 1: h = Zs @ W2 + b2 ---
    {
        const int mW = (wid >> 1) * 32;
        const int nW = (wid & 1) * 32;
        float acc[2][4][4];
#pragma unroll
        for (int i = 0; i < 2; i++)
#pragma unroll
            for (int j = 0; j < 4; j++)
#pragma unroll
                for (int q = 0; q < 4; q++) acc[i][j][q] = 0.f;
#pragma unroll
        for (int ks = 0; ks < 8; ks++) {
            uint32_t a[2][4], b[4][2];
#pragma unroll
            for (int i = 0; i < 2; i++) {
                int r0 = mW + i * 16 + g;
                a[i][0] = Zs[r0 * 68 + ks * 8 + tg];
                a[i][1] = Zs[(r0 + 8) * 68 + ks * 8 + tg];
                a[i][2] = Zs[r0 * 68 + ks * 8 + tg + 4];
                a[i][3] = Zs[(r0 + 8) * 68 + ks * 8 + tg + 4];
            }
#pragma unroll
            for (int j = 0; j < 4; j++) {
                b[j][0] = W2s[(ks * 8 + tg) * 72 + nW + j * 8 + g];
                b[j][1] = W2s[(ks * 8 + tg + 4) * 72 + nW + j * 8 + g];
            }
#pragma unroll
            for (int i = 0; i < 2; i++)
#pragma unroll
                for (int j = 0; j < 4; j++)
                    mma8(acc[i][j], a[i], b[j]);
        }
        __syncthreads();
#pragma unroll
        for (int i = 0; i < 2; i++) {
            int lr0 = mW + i * 16 + g, lr1 = lr0 + 8;
            int r0 = rowBase + lr0, r1 = rowBase + lr1;
#pragma unroll
            for (int j = 0; j < 4; j++) {
                int c = nW + j * 8 + tg * 2;
                float bi0 = __ldg(b2 + c), bi1 = __ldg(b2 + c + 1);
                float h0 = acc[i][j][0] + bi0, h1 = acc[i][j][1] + bi1;
                float h2 = acc[i][j][2] + bi0, h3 = acc[i][j][3] + bi1;
                Zs[lr0 * 68 + c] = f2tf(h0); Zs[lr0 * 68 + c + 1] = f2tf(h1);
                Zs[lr1 * 68 + c] = f2tf(h2); Zs[lr1 * 68 + c + 1] = f2tf(h3);
                if (r0 < M)
                    *reinterpret_cast<float2*>(h_out + (size_t)r0 * HID + c) = make_float2(h0, h1);
                if (r1 < M)
                    *reinterpret_cast<float2*>(h_out + (size_t)r1 * HID + c) = make_float2(h2, h3);
            }
        }
    }
    __syncthreads();

    // --- stage 2: [u_pos | u_self] = h @ [Wp1|Ws1] ---
    {
        const int mW = (wid >> 2) * 64;
        const int nW = (wid & 3) * 32;
        float acc[4][4][4];
#pragma unroll
        for (int i = 0; i < 4; i++)
#pragma unroll
            for (int j = 0; j < 4; j++)
#pragma unroll
                for (int q = 0; q < 4; q++) acc[i][j][q] = 0.f;
#pragma unroll
        for (int ks = 0; ks < 8; ks++) {
            uint32_t a[4][4], b[4][2];
#pragma unroll
            for (int i = 0; i < 4; i++) {
                int r0 = mW + i * 16 + g;
                a[i][0] = Zs[r0 * 68 + ks * 8 + tg];
                a[i][1] = Zs[(r0 + 8) * 68 + ks * 8 + tg];
                a[i][2] = Zs[r0 * 68 + ks * 8 + tg + 4];
                a[i][3] = Zs[(r0 + 8) * 68 + ks * 8 + tg + 4];
            }
#pragma unroll
            for (int j = 0; j < 4; j++) {
                b[j][0] = W13[(ks * 8 + tg) * 136 + nW + j * 8 + g];
                b[j][1] = W13[(ks * 8 + tg + 4) * 136 + nW + j * 8 + g];
            }
#pragma unroll
            for (int i = 0; i < 4; i++)
#pragma unroll
                for (int j = 0; j < 4; j++)
                    mma8(acc[i][j], a[i], b[j]);
        }
        __syncthreads();
#pragma unroll
        for (int i = 0; i < 4; i++) {
            int lr0 = mW + i * 16 + g, lr1 = lr0 + 8;
            int r0 = rowBase + lr0, r1 = rowBase + lr1;
#pragma unroll
            for (int j = 0; j < 4; j++) {
                int c = nW + j * 8 + tg * 2;
                if (c < 64) {
                    float bi0 = __ldg(bp1 + c), bi1 = __ldg(bp1 + c + 1);
                    upos[lr0 * 65 + c]     = fmaxf(acc[i][j][0] + bi0, 0.f);
                    upos[lr0 * 65 + c + 1] = fmaxf(acc[i][j][1] + bi1, 0.f);
                    upos[lr1 * 65 + c]     = fmaxf(acc[i][j][2] + bi0, 0.f);
                    upos[lr1 * 65 + c + 1] = fmaxf(acc[i][j][3] + bi1, 0.f);
                } else {
                    int cc = c - 64;
                    float bi0 = __ldg(bs1 + cc), bi1 = __ldg(bs1 + cc + 1);
                    float o0 = roundtf(fmaxf(acc[i][j][0] + bi0, 0.f));
                    float o1 = roundtf(fmaxf(acc[i][j][1] + bi1, 0.f));
                    float o2 = roundtf(fmaxf(acc[i][j][2] + bi0, 0.f));
                    float o3 = roundtf(fmaxf(acc[i][j][3] + bi1, 0.f));
                    if (r0 < M)
                        *reinterpret_cast<float2*>(uself + (size_t)r0 * HID + cc) = make_float2(o0, o1);
                    if (r1 < M)
                        *reinterpret_cast<float2*>(uself + (size_t)r1 * HID + cc) = make_float2(o2, o3);
                }
            }
        }
    }
    __syncthreads();

    // --- pos head: pos = upos @ Wp2 + bp2 ---
    if (tid < 128) {
        int r = rowBase + tid;
        if (r < M) {
            float p0 = __ldg(bp2), p1 = __ldg(bp2 + 1);
#pragma unroll
            for (int k = 0; k < HID; k++) {
                float v = upos[tid * 65 + k];
                p0 = fmaf(v, __ldg(Wp2 + k * 2), p0);
                p1 = fmaf(v, __ldg(Wp2 + k * 2 + 1), p1);
            }
            pos_out[(size_t)r * 2]     = p0;
            pos_out[(size_t)r * 2 + 1] = p1;
        }
    }
}

// ---------------- single-kernel BatchNorm stats (last-block reduce) ------
__global__ __launch_bounds__(256)
void bn_fused(const float* __restrict__ z,
              const float* __restrict__ gamma, const float* __restrict__ beta)
{
    __shared__ float sh1[4][64], sh2[4][64];
    __shared__ unsigned done;
    const int t = threadIdx.x;
    const int c = t & 63, q = t >> 6;
    const int b = blockIdx.x;

    float s = 0.f, ss = 0.f;
    int r0 = b * 100 + q * 25;
    for (int r = r0; r < r0 + 25; r++) {
        float v = z[(size_t)r * HID + c];
        s += v; ss += v * v;
    }
    sh1[q][c] = s; sh2[q][c] = ss;
    __syncthreads();
    if (q == 0) {
        s  = sh1[0][c] + sh1[1][c] + sh1[2][c] + sh1[3][c];
        ss = sh2[0][c] + sh2[1][c] + sh2[2][c] + sh2[3][c];
        g_part[b * 128 + c]      = s;
        g_part[b * 128 + 64 + c] = ss;
    }
    __threadfence();
    __syncthreads();
    if (t == 0) done = atomicInc(&g_bnctr, 499);
    __syncthreads();
    if (done == 499) {
        float s2 = 0.f, ss2 = 0.f;
        for (int bb = q; bb < 500; bb += 4) {
            s2  += g_part[bb * 128 + c];
            ss2 += g_part[bb * 128 + 64 + c];
        }
        sh1[q][c] = s2; sh2[q][c] = ss2;
        __syncthreads();
        if (q == 0) {
            float S  = sh1[0][c] + sh1[1][c] + sh1[2][c] + sh1[3][c];
            float SS = sh2[0][c] + sh2[1][c] + sh2[2][c] + sh2[3][c];
            float mu = S / (float)NSPOT;
            float var = SS / (float)NSPOT - mu * mu;
            float rstd = rsqrtf(var + BN_EPS);
            float sc = gamma[c] * rstd;
            g_sc[c] = sc;
            g_sh[c] = beta[c] - mu * sc;
        }
    }
}

// ---------------- pre-round one B matrix -------------------------------
__global__ __launch_bounds__(256)
void prep_w(const float* __restrict__ src, float* __restrict__ dst)
{
    int i = blockIdx.x * blockDim.x + threadIdx.x;
    if (i < HID * NGENE) dst[i] = roundtf(src[i]);
}

// ---------------- per-destination edge counts (input-only) --------------
__global__ __launch_bounds__(256)
void cnt_count(const int* __restrict__ ei)
{
    int e = blockIdx.x * blockDim.x + threadIdx.x;
    if (e < NEDGE) atomicAdd(&g_cnt[__ldg(ei + NEDGE + e)], 1);
}

// ---------------- edge aggregation (values only) -------------------------
__global__ void scatter_h(const float* __restrict__ h, const int* __restrict__ ei)
{
    long t = (long)blockIdx.x * blockDim.x + threadIdx.x;
    if (t >= (long)NEDGE * 16) return;
    int e = (int)(t >> 4), p = (int)(t & 15);
    int src = __ldg(ei + e);
    int dst = __ldg(ei + NEDGE + e);
    float4 v = *reinterpret_cast<const float4*>(h + (size_t)src * HID + p * 4);
    float* a = g_agg + (size_t)dst * HID + p * 4;
    asm volatile("red.global.add.v4.f32 [%0], {%1,%2,%3,%4};"
                 :: "l"(a), "f"(v.x), "f"(v.y), "f"(v.z), "f"(v.w) : "memory");
}

// ---------------- launch ---------------------------------------------------
extern "C" void kernel_launch(void* const* d_in, const int* in_sizes, int n_in,
                              void* d_out, int out_size)
{
    const float* x     = (const float*)d_in[0];
    const int*   ei    = (const int*)  d_in[1];
    const float* W1    = (const float*)d_in[2];
    const float* b1    = (const float*)d_in[3];
    const float* gamma = (const float*)d_in[4];
    const float* beta  = (const float*)d_in[5];
    const float* W2    = (const float*)d_in[6];
    const float* b2    = (const float*)d_in[7];
    const float* Wp1   = (const float*)d_in[8];
    const float* bp1   = (const float*)d_in[9];
    const float* Wp2   = (const float*)d_in[10];
    const float* bp2   = (const float*)d_in[11];
    const float* Ws1   = (const float*)d_in[12];
    const float* bs1   = (const float*)d_in[13];
    const float* Ws2   = (const float*)d_in[14];
    const float* bs2   = (const float*)d_in[15];
    const float* We1   = (const float*)d_in[16];
    const float* be1   = (const float*)d_in[17];
    const float* We2   = (const float*)d_in[18];
    const float* be2   = (const float*)d_in[19];

    float* out = (float*)d_out;
    float* h_out   = out;
    float* pos_out = out + (size_t)NSPOT * HID;
    float* xs_out  = pos_out + (size_t)NSPOT * 2;
    float* xn_out  = xs_out + (size_t)NSPOT * NGENE;

    float* zp;   cudaGetSymbolAddress((void**)&zp, g_z);
    float* usp;  cudaGetSymbolAddress((void**)&usp, g_uself);
    float* aggp; cudaGetSymbolAddress((void**)&aggp, g_agg);
    int*   cntp; cudaGetSymbolAddress((void**)&cntp, g_cnt);
    float* wbp;  cudaGetSymbolAddress((void**)&wbp, g_wb);

    const int MB128 = (NSPOT + 127) / 128;   // 391
    dim3 gN64(1, MB128);
    dim3 gBig((NGENE + 127) / 128, MB128);   // 16 x 391

    constexpr int SMEM_G1  = 2 * (128 * 36 + 32 * 72)  * 4;   // 55296
    constexpr int SMEM_BIG = 2 * (128 * 36 + 32 * 136) * 4;   // 71680
    constexpr int SMEMF    = (128 * 68 + 64 * 72 + 64 * 136) * 4;  // 88064
    cudaFuncSetAttribute((const void*)gemm_db<64, false, true, false>,
                         cudaFuncAttributeMaxDynamicSharedMemorySize, SMEM_G1);
    cudaFuncSetAttribute((const void*)gemm_db<128, false, false, true>,
                         cudaFuncAttributeMaxDynamicSharedMemorySize, SMEM_BIG);
    cudaFuncSetAttribute(fused_enc, cudaFuncAttributeMaxDynamicSharedMemorySize, SMEMF);

    // zero agg scratch via memset nodes (not kernel launches)
    cudaMemsetAsync(aggp, 0, (size_t)NSPOT * HID * sizeof(float));
    cudaMemsetAsync(cntp, 0, (size_t)NSPOT * sizeof(int));

    // k1-k2. pre-round Ws2 / We2 (input-only)
    prep_w<<<(HID * NGENE + 255) / 256, 256>>>(Ws2, wbp);
    prep_w<<<(HID * NGENE + 255) / 256, 256>>>(We2, wbp + HID * NGENE);
    // k3. per-destination edge counts (input-only)
    cnt_count<<<(NEDGE + 255) / 256, 256>>>(ei);
    // k4. z = x @ W1 + b1   <-- ncu capture slot (first profile of gemm1!)
    gemm_db<64, false, true, false><<<gN64, 256, SMEM_G1>>>(x, W1, b1, zp,
                                                            NSPOT, HID, NGENE);
    // k5. BN stats -> scale/shift
    bn_fused<<<500, 256>>>(zp, gamma, beta);
    // k6. fused encoder tail: h, pos, u_self
    fused_enc<<<MB128, 256, SMEMF>>>(zp, W2, b2, Wp1, bp1, Ws1, bs1, Wp2, bp2,
                                     h_out, pos_out, usp, NSPOT);
    // k7. xs = u_self @ Ws2r + bs2  (streaming stores)
    gemm_db<128, false, false, true><<<gBig, 256, SMEM_BIG>>>(usp, wbp, bs2, xs_out,
                                                              NSPOT, NGENE, HID);
    // k8. neighbor aggregation (values only; counts already done)
    {
        long tot = (long)NEDGE * 16;
        scatter_h<<<(int)((tot + 255) / 256), 256>>>(h_out, ei);
    }
    // k9. u_nb = relu(mean(agg) @ We1 + be1) -> g_z (tf32-pre-rounded)
    gemm_tf32<128, 64, 32, true, 2, true><<<gN64, 256>>>(aggp, We1, be1, zp,
                                                         NSPOT, HID, HID);
    // k10. xn = u_nb @ We2r + be2  (streaming stores)
    gemm_db<128, false, false, true><<<gBig, 256, SMEM_BIG>>>(zp, wbp + HID * NGENE,
                                                              be2, xn_out,
                                                              NSPOT, NGENE, HID);

    (void)in_sizes; (void)n_in; (void)out_size;
}